// round 12
// baseline (speedup 1.0000x reference)
#include <cuda_runtime.h>
#include <cstdint>
#include <math.h>
#include <cstdio>
#include <cstdlib>

#define NBATCH 16
#define RPB    1024
#define MROW   (NBATCH*RPB)
#define KDIM   512
#define NSLOT  5
#define NPB    (RPB*KDIM)
#define NPB4   (NPB/4)
#define CPB    32                  // gram chunks per batch
#define NJOBS  512                 // 128 M-tiles x 4 N-tiles
#define NCOMBO 512                 // combo chunks (16 batches x 32 segments)
#define GRID_BLOCKS 256
#define LAMBDA 1e-4
#define TOLV   0.01

#define BM 128
#define BN 128
#define BK 16

__device__ __align__(16) float  g_Fm[NBATCH*NSLOT*NPB];
__device__ __align__(16) float  g_G [NBATCH*NSLOT*NPB];
__device__ __align__(16) float  g_xlast[MROW*KDIM];
__device__ double g_gram_part[NBATCH*CPB*5];
__device__ double g_res_part[NJOBS*2];
__device__ double g_diag[1024];
__device__ unsigned g_barCount = 0;
__device__ volatile unsigned g_barFlag = 0;
__device__ unsigned g_jobCtr = 0;

// ---- fast grid barrier: atomic arrival, volatile-spin wait, ctr reset ------
__device__ __forceinline__ void gridBar(unsigned& gen) {
    __syncthreads();
    if (threadIdx.x == 0) {
        __threadfence();
        unsigned old = atomicAdd(&g_barCount, 1u);
        if (old == GRID_BLOCKS - 1u) {
            g_barCount = 0;            // no contender until flag flips
            g_jobCtr   = 0;            // phase job counter reset
            __threadfence();
            g_barFlag  = gen + 1u;     // release
        } else {
            while (g_barFlag < gen + 1u) { }
            __threadfence();           // acquire
        }
        gen += 1u;
    }
    __syncthreads();
}

// ---- packed f32x2 helpers ---------------------------------------------------
__device__ __forceinline__ unsigned long long pk2(float x, float y) {
    unsigned long long r;
    asm("mov.b64 %0, {%1, %2};" : "=l"(r) : "f"(x), "f"(y));
    return r;
}
__device__ __forceinline__ void upk2(unsigned long long v, float& x, float& y) {
    asm("mov.b64 {%0, %1}, %2;" : "=f"(x), "=f"(y) : "l"(v));
}
__device__ __forceinline__ void ffma2(unsigned long long& d,
                                      unsigned long long a, unsigned long long b) {
    asm("fma.rn.f32x2 %0, %1, %2, %0;" : "+l"(d) : "l"(a), "l"(b));
}

__device__ __forceinline__ const float* resolveRow(const float* A, int aMode,
                                                   int aSlot, int r) {
    if (aMode == 1) {
        int b = r >> 10, rr = r & 1023;
        return g_Fm + ((size_t)(b*NSLOT + aSlot))*NPB + (size_t)rr*KDIM;
    } else if (aMode == 2) {
        return g_xlast + (size_t)r*KDIM;
    }
    return A + (size_t)r*KDIM;
}

__device__ __forceinline__ float4 ld4(const float* p, bool bypass) {
    return bypass ? __ldcg((const float4*)p) : *(const float4*)p;
}

__device__ __forceinline__ float4 unpack4(const unsigned long long* a, int half,
                                          float4 bv) {
    float4 v; float lo, hi;
    upk2(a[0], lo, hi); v.x = (half ? hi : lo) + bv.x;
    upk2(a[1], lo, hi); v.y = (half ? hi : lo) + bv.y;
    upk2(a[2], lo, hi); v.z = (half ? hi : lo) + bv.z;
    upk2(a[3], lo, hi); v.w = (half ? hi : lo) + bv.w;
    return v;
}

// ---------------------------------------------------------------------------
// One 128x128 GEMM tile job (math identical to round-9 gemm128).
// Cross-block global reads use .cg (L1 incoherent within a launch).
// ---------------------------------------------------------------------------
__device__ void gemmJob(int job,
                        const float* __restrict__ A, int aMode, int aSlot,
                        const float* __restrict__ W, const float* __restrict__ bias,
                        float* __restrict__ outPlain, int outSlot,
                        float (*As)[BM], float (*Bs)[BN], double (*sred)[6])
{
    const int tid = threadIdx.x;
    const int my  = job >> 2;
    const int nx  = job & 3;
    const int m0  = my * BM;
    const int n0  = nx * BN;
    const int tx  = tid & 15;
    const int ty  = tid >> 4;
    const int lr  = tid >> 1;
    const int lk  = (tid & 1) << 3;
    const bool byp = (aMode != 0);

    const float* aRow = resolveRow(A, aMode, aSlot, m0 + lr);
    const float* wRow = W + (size_t)(n0 + lr)*KDIM;

    unsigned long long acc[4][8];
#pragma unroll
    for (int ip = 0; ip < 4; ip++)
#pragma unroll
        for (int j = 0; j < 8; j++) acc[ip][j] = 0ULL;

    float4 pa0 = ld4(aRow + lk, byp);
    float4 pa1 = ld4(aRow + lk + 4, byp);
    float4 pb0 = *(const float4*)(wRow + lk);
    float4 pb1 = *(const float4*)(wRow + lk + 4);

    for (int k0 = 0; k0 < KDIM; k0 += BK) {
        As[lk+0][lr]=pa0.x; As[lk+1][lr]=pa0.y; As[lk+2][lr]=pa0.z; As[lk+3][lr]=pa0.w;
        As[lk+4][lr]=pa1.x; As[lk+5][lr]=pa1.y; As[lk+6][lr]=pa1.z; As[lk+7][lr]=pa1.w;
        Bs[lk+0][lr]=pb0.x; Bs[lk+1][lr]=pb0.y; Bs[lk+2][lr]=pb0.z; Bs[lk+3][lr]=pb0.w;
        Bs[lk+4][lr]=pb1.x; Bs[lk+5][lr]=pb1.y; Bs[lk+6][lr]=pb1.z; Bs[lk+7][lr]=pb1.w;
        __syncthreads();

        if (k0 + BK < KDIM) {
            pa0 = ld4(aRow + k0 + BK + lk, byp);
            pa1 = ld4(aRow + k0 + BK + lk + 4, byp);
            pb0 = *(const float4*)(wRow + k0 + BK + lk);
            pb1 = *(const float4*)(wRow + k0 + BK + lk + 4);
        }

#pragma unroll
        for (int kk = 0; kk < BK; kk++) {
            float2 a0 = *(const float2*)&As[kk][ty*4];
            float2 a1 = *(const float2*)&As[kk][ty*4 + 2];
            float2 a2 = *(const float2*)&As[kk][64 + ty*4];
            float2 a3 = *(const float2*)&As[kk][64 + ty*4 + 2];
            float4 b03 = *(const float4*)&Bs[kk][tx*4];
            float4 b47 = *(const float4*)&Bs[kk][64 + tx*4];

            unsigned long long ap[4];
            ap[0] = pk2(a0.x, a0.y); ap[1] = pk2(a1.x, a1.y);
            ap[2] = pk2(a2.x, a2.y); ap[3] = pk2(a3.x, a3.y);
            unsigned long long bb[8];
            bb[0]=pk2(b03.x,b03.x); bb[1]=pk2(b03.y,b03.y);
            bb[2]=pk2(b03.z,b03.z); bb[3]=pk2(b03.w,b03.w);
            bb[4]=pk2(b47.x,b47.x); bb[5]=pk2(b47.y,b47.y);
            bb[6]=pk2(b47.z,b47.z); bb[7]=pk2(b47.w,b47.w);

#pragma unroll
            for (int ip = 0; ip < 4; ip++)
#pragma unroll
                for (int j = 0; j < 8; j++)
                    ffma2(acc[ip][j], ap[ip], bb[j]);
        }
        __syncthreads();
    }

    double sg[5] = {0,0,0,0,0};
    double sd = 0.0;

#pragma unroll
    for (int ip = 0; ip < 4; ip++) {
        const int rbase = ((ip & 2) ? 64 : 0) + ty*4 + ((ip & 1) ? 2 : 0);
#pragma unroll
        for (int half = 0; half < 2; half++) {
            const int r = m0 + rbase + half;
            if (outSlot >= 0) {
                const float* aR = resolveRow(A, aMode, aSlot, r);
                int b = r >> 10, rr = r & 1023;
                size_t gbase = (size_t)(b*NSLOT)*NPB + (size_t)rr*KDIM;
                size_t obase = gbase + (size_t)outSlot*NPB;
#pragma unroll
                for (int jg = 0; jg < 2; jg++) {
                    const int c = n0 + jg*64 + tx*4;
                    float4 av = ld4(aR + c, byp);
                    float4 bv = *(const float4*)(bias + c);
                    float4 val = unpack4(&acc[ip][jg*4], half, bv);
                    float4 g4;
                    g4.x = val.x - av.x; g4.y = val.y - av.y;
                    g4.z = val.z - av.z; g4.w = val.w - av.w;
                    *(float4*)(g_Fm + obase + c) = val;
                    *(float4*)(g_G  + obase + c) = g4;
#pragma unroll
                    for (int j = 0; j < 5; j++) {
                        float4 gj;
                        if (j == outSlot) gj = g4;
                        else gj = __ldcg((const float4*)(g_G + gbase + (size_t)j*NPB + c));
                        sg[j] += (double)(g4.x*gj.x + g4.y*gj.y
                                        + g4.z*gj.z + g4.w*gj.w);
                    }
                    sd += (double)(val.x*val.x + val.y*val.y
                                 + val.z*val.z + val.w*val.w);
                }
            } else {
#pragma unroll
                for (int jg = 0; jg < 2; jg++) {
                    const int c = n0 + jg*64 + tx*4;
                    float4 bv = *(const float4*)(bias + c);
                    float4 val = unpack4(&acc[ip][jg*4], half, bv);
                    *(float4*)(outPlain + (size_t)r*KDIM + c) = val;
                }
            }
        }
    }

    if (outSlot >= 0) {
        const unsigned FULL = 0xFFFFFFFFu;
#pragma unroll
        for (int p = 0; p < 5; p++)
#pragma unroll
            for (int o = 16; o > 0; o >>= 1)
                sg[p] += __shfl_down_sync(FULL, sg[p], o);
#pragma unroll
        for (int o = 16; o > 0; o >>= 1)
            sd += __shfl_down_sync(FULL, sd, o);

        const int wid = tid >> 5, lane = tid & 31;
        if (lane == 0) {
#pragma unroll
            for (int p = 0; p < 5; p++) sred[wid][p] = sg[p];
            sred[wid][5] = sd;
        }
        __syncthreads();
        if (tid < 6) {
            double v = 0.0;
#pragma unroll
            for (int w = 0; w < 8; w++) v += sred[w][tid];
            const int b = my >> 3;
            const int chunk = ((my & 7) << 2) | nx;
            if (tid < 5) {
                g_gram_part[((size_t)(b*CPB + chunk))*5 + tid] = v;
                if (tid == outSlot) g_res_part[2*job] = v;
            } else {
                g_res_part[2*job + 1] = v;
            }
        }
        __syncthreads();
    }
}

// ---- work-stealing wrapper: blocks drain the global job queue --------------
__device__ void stealGemm(const float* A, int aMode, int aSlot,
                          const float* W, const float* bias,
                          float* outPlain, int outSlot,
                          float (*As)[BM], float (*Bs)[BN], double (*sred)[6],
                          int* sJob)
{
    for (;;) {
        if (threadIdx.x == 0) *sJob = (int)atomicAdd(&g_jobCtr, 1u);
        __syncthreads();
        int job = *sJob;
        __syncthreads();
        if (job >= NJOBS) break;
        gemmJob(job, A, aMode, aSlot, W, bias, outPlain, outSlot, As, Bs, sred);
    }
}

// ---------------------------------------------------------------------------
// Redundant per-block phases (identical fp sequence in every block)
// ---------------------------------------------------------------------------
__device__ void foldLocal(double (*sTab)[15], int idxPrev)
{
    const int tid = threadIdx.x;
    if (tid < 80) {
        int b = tid / 5, j = tid % 5;
        double v = 0.0;
#pragma unroll
        for (int c = 0; c < CPB; c++)
            v += __ldcg(&g_gram_part[((size_t)(b*CPB + c))*5 + j]);
        int i_ = idxPrev < j ? idxPrev : j;
        int j_ = idxPrev < j ? j : idxPrev;
        int p = i_*5 - i_*(i_-1)/2 + (j_ - i_);
        sTab[b][p] = v;
    }
}

__device__ double reduceRes(double* sh)
{
    const int tid = threadIdx.x;
    double sn = 0.0, sd = 0.0;
#pragma unroll
    for (int t = 0; t < 2; t++) {
        int i = t*256 + tid;
        sn += __ldcg(&g_res_part[2*i]);
        sd += __ldcg(&g_res_part[2*i+1]);
    }
    sh[tid] = sn; __syncthreads();
    for (int s = 128; s > 0; s >>= 1) { if (tid < s) sh[tid] += sh[tid+s]; __syncthreads(); }
    double tsn = sh[0]; __syncthreads();
    sh[tid] = sd; __syncthreads();
    for (int s = 128; s > 0; s >>= 1) { if (tid < s) sh[tid] += sh[tid+s]; __syncthreads(); }
    double r = sqrt(fmax(tsn, 0.0)) / (1e-5 + sqrt(fmax(sh[0], 0.0)));
    __syncthreads();
    return r;   // identical in every block
}

__device__ void choleskyAll(double (*sTab)[15], float (*sAlpha)[5], int nk)
{
    const int tid = threadIdx.x;
    if (tid < NBATCH) {
        const int b = tid;
        double Afull[5][5];
        {
            int p = 0;
            for (int i = 0; i < 5; i++)
                for (int j = i; j < 5; j++) {
                    double v = sTab[b][p]; p++;
                    Afull[i][j] = v; Afull[j][i] = v;
                }
            for (int i = 0; i < 5; i++) Afull[i][i] += LAMBDA;
        }
        double L[5][5];
        for (int c = 0; c < nk; c++) {
            double d = Afull[c][c];
            for (int q = 0; q < c; q++) d -= L[c][q]*L[c][q];
            d = sqrt(fmax(d, 1e-300));
            L[c][c] = d;
            for (int r = c+1; r < nk; r++) {
                double v = Afull[r][c];
                for (int q = 0; q < c; q++) v -= L[r][q]*L[c][q];
                L[r][c] = v / d;
            }
        }
        double y[5];
        for (int r = 0; r < nk; r++) {
            double v = 1.0;
            for (int j = 0; j < r; j++) v -= L[r][j]*y[j];
            y[r] = v / L[r][r];
        }
        double z[5];
        for (int r = nk-1; r >= 0; r--) {
            double v = y[r];
            for (int j = r+1; j < nk; j++) v -= L[j][r]*z[j];
            z[r] = v / L[r][r];
        }
        double S = 0.0;
        for (int r = 0; r < nk; r++) S += z[r];
        for (int m = 0; m < 5; m++)
            sAlpha[b][m] = (m < nk) ? (float)(z[m]/S) : 0.f;
    }
}

// ---- combo with stealing: 512 chunks of 4096 float4 ------------------------
__device__ void comboSteal(int nk, float (*sAlpha)[5], int* sJob)
{
    const int tid = threadIdx.x;
    for (;;) {
        if (tid == 0) *sJob = (int)atomicAdd(&g_jobCtr, 1u);
        __syncthreads();
        int job = *sJob;
        __syncthreads();
        if (job >= NCOMBO) break;

        const int b   = job >> 5;
        const int seg = job & 31;
        float al[5];
#pragma unroll
        for (int m = 0; m < 5; m++) al[m] = sAlpha[b][m];
        const float4* Fb = ((const float4*)g_Fm) + (size_t)b*NSLOT*NPB4;
#pragma unroll 4
        for (int t = 0; t < 16; t++) {
            int off = seg*4096 + t*256 + tid;
            float4 acc = make_float4(0.f,0.f,0.f,0.f);
#pragma unroll
            for (int m = 0; m < 5; m++) {
                if (m < nk) {
                    float4 v = __ldcg(&Fb[(size_t)m*NPB4 + off]);
                    acc.x = fmaf(al[m], v.x, acc.x);
                    acc.y = fmaf(al[m], v.y, acc.y);
                    acc.z = fmaf(al[m], v.z, acc.z);
                    acc.w = fmaf(al[m], v.w, acc.w);
                }
            }
            ((float4*)g_xlast)[(size_t)b*NPB4 + off] = acc;
        }
    }
}

// ---------------------------------------------------------------------------
// persistent mega-kernel v3: redundant solve + work stealing + fast barrier
// ---------------------------------------------------------------------------
__global__ __launch_bounds__(256, 2) void megaK(
    const float* __restrict__ x, const float* __restrict__ lin_w,
    const float* __restrict__ lin_b, const float* __restrict__ weight,
    const float* __restrict__ bias, float* __restrict__ out)
{
    __shared__ __align__(16) float As[BK][BM];
    __shared__ __align__(16) float Bs[BK][BN];
    __shared__ double sred[8][6];
    __shared__ double sh[256];
    __shared__ double sTab[NBATCH][15];
    __shared__ float  sAlpha[NBATCH][5];
    __shared__ int    sJob;

    unsigned gen = 0;
    if (threadIdx.x == 0) gen = g_barFlag;   // all blocks read before any flip

    if (blockIdx.x == 0 && threadIdx.x == 0) g_diag[20] = -1.0;

    // init: Fm0 = f(x)   (g_jobCtr is 0 at kernel entry by invariant)
    stealGemm(x, 0, 0, lin_w, lin_b, nullptr, 0, As, Bs, sred, &sJob);
    gridBar(gen);
    foldLocal(sTab, 0);
    gridBar(gen);   // folds complete before slot-1 gemm overwrites partials
    stealGemm(nullptr, 1, 0, lin_w, lin_b, nullptr, 1, As, Bs, sred, &sJob);
    gridBar(gen);

    for (int k = 2; k < 50; k++) {
        const int nk = (k < 5) ? k : 5;
        const int idx = k % 5;
        const int idxPrev = (k == 2) ? 1 : ((k - 1) % 5);

        if (k > 2) {
            double res = reduceRes(sh);
            if (blockIdx.x == 0 && threadIdx.x == 0)
                g_diag[700 + (size_t)(k-2)] = res;
            if (res < TOLV) {
                if (blockIdx.x == 0 && threadIdx.x == 0) g_diag[20] = (double)k;
                break;   // identical decision in every block
            }
        }
        foldLocal(sTab, idxPrev);
        __syncthreads();
        choleskyAll(sTab, sAlpha, nk);
        __syncthreads();

        comboSteal(nk, sAlpha, &sJob);
        gridBar(gen);      // xlast complete; ctr reset

        stealGemm(nullptr, 2, 0, lin_w, lin_b, nullptr, idx, As, Bs, sred, &sJob);
        gridBar(gen);      // partials complete; ctr reset (0 for next phase/exit)
    }

    // out = xlast @ weight^T + bias  (fixed mapping: leaves ctr at 0 for replays)
    for (int jj = 0; jj < 2; jj++)
        gemmJob(blockIdx.x + jj*GRID_BLOCKS, nullptr, 2, 0, weight, bias, out, -1,
                As, Bs, sred);
}

// ---------------------------------------------------------------------------
extern "C" void kernel_launch(void* const* d_in, const int* in_sizes, int n_in,
                              void* d_out, int out_size)
{
    const float* x      = (const float*)d_in[0];
    const float* lin_w  = (const float*)d_in[1];
    const float* lin_b  = (const float*)d_in[2];
    const float* weight = (const float*)d_in[3];
    const float* bias   = (const float*)d_in[4];
    float* out = (float*)d_out;

    cudaStreamCaptureStatus cap = cudaStreamCaptureStatusNone;
    cudaStreamIsCapturing(0, &cap);
    const bool capturing = (cap != cudaStreamCaptureStatusNone);

    megaK<<<GRID_BLOCKS, 256>>>(x, lin_w, lin_b, weight, bias, out);

    // Fail-only diagnostics (zero cost when converged).
    if (!capturing) {
        cudaDeviceSynchronize();
        static double h[1024];
        cudaMemcpyFromSymbol(h, g_diag, sizeof(h));
        if (h[20] < 0.0) {
            for (int k = 49; k >= 3; k--)
                fprintf(stderr, "D k=%d res=%.3e\n", k, h[700 + (size_t)(k-2)]);
            fprintf(stderr, "D SUMMARY convk=%.0f\n", h[20]);
            fflush(stderr);
            exit(42);
        }
    }
}

// round 13
// speedup vs baseline: 1.2120x; 1.2120x over previous
#include <cuda_runtime.h>
#include <cstdint>
#include <math.h>
#include <cstdio>
#include <cstdlib>

#define NBATCH 16
#define RPB    1024
#define MROW   (NBATCH*RPB)
#define KDIM   512
#define NSLOT  5
#define NPB    (RPB*KDIM)
#define NPB4   (NPB/4)
#define CPB    32                   // gram chunks per batch
#define BODY_BLOCKS 512             // gemm grid = 4 x 128
#define LAMBDA 1e-4
#define TOLV   0.01

__device__ __align__(16) float  g_Fm[NBATCH*NSLOT*NPB];
__device__ __align__(16) float  g_G [NBATCH*NSLOT*NPB];
__device__ __align__(16) float  g_xlast[MROW*KDIM];
__device__ double g_gram_part[NBATCH*CPB*5];   // fresh pairs (idx, j)
__device__ double g_gramTab[NBATCH*15];        // persistent Gram table
__device__ double g_res_part[BODY_BLOCKS*2];
__device__ int    g_converged;
__device__ double g_diag[1024];

__global__ void resetK() {
    g_converged = 0;
    g_diag[20] = -1.0;
}

// ---- packed f32x2 helpers (sm_103a) ----------------------------------------
__device__ __forceinline__ unsigned long long pk2(float x, float y) {
    unsigned long long r;
    asm("mov.b64 %0, {%1, %2};" : "=l"(r) : "f"(x), "f"(y));
    return r;
}
__device__ __forceinline__ void upk2(unsigned long long v, float& x, float& y) {
    asm("mov.b64 {%0, %1}, %2;" : "=f"(x), "=f"(y) : "l"(v));
}
__device__ __forceinline__ void ffma2(unsigned long long& d,
                                      unsigned long long a, unsigned long long b) {
    asm("fma.rn.f32x2 %0, %1, %2, %0;" : "+l"(d) : "l"(a), "l"(b));
}

#define BM 128
#define BN 128
#define BK 16

__device__ __forceinline__ const float* resolveRow(const float* A, int aMode,
                                                   int aSlot, int r) {
    if (aMode == 1) {
        int b = r >> 10, rr = r & 1023;
        return g_Fm + ((size_t)(b*NSLOT + aSlot))*NPB + (size_t)rr*KDIM;
    } else if (aMode == 2) {
        return g_xlast + (size_t)r*KDIM;
    }
    return A + (size_t)r*KDIM;
}

__device__ __forceinline__ float4 unpack4(const unsigned long long* a, int half,
                                          float4 bv) {
    float4 v; float lo, hi;
    upk2(a[0], lo, hi); v.x = (half ? hi : lo) + bv.x;
    upk2(a[1], lo, hi); v.y = (half ? hi : lo) + bv.y;
    upk2(a[2], lo, hi); v.z = (half ? hi : lo) + bv.z;
    upk2(a[3], lo, hi); v.w = (half ? hi : lo) + bv.w;
    return v;
}

// ---------------------------------------------------------------------------
// Fused GEMM (byte-identical math to round-9 gemm128)
// ---------------------------------------------------------------------------
__global__ __launch_bounds__(256, 2) void gemm128(
    const float* __restrict__ A, int aMode, int aSlot,
    const float* __restrict__ W, const float* __restrict__ bias,
    float* __restrict__ outPlain, int outSlot, int doGuard)
{
    if (doGuard && g_converged) return;

    __shared__ __align__(16) float As[BK][BM];
    __shared__ __align__(16) float Bs[BK][BN];
    __shared__ double sred[8][6];

    const int tid = threadIdx.x;
    const int m0  = blockIdx.y * BM;
    const int n0  = blockIdx.x * BN;
    const int tx  = tid & 15;
    const int ty  = tid >> 4;
    const int lr  = tid >> 1;
    const int lk  = (tid & 1) << 3;

    const float* aRow = resolveRow(A, aMode, aSlot, m0 + lr);
    const float* wRow = W + (size_t)(n0 + lr)*KDIM;

    unsigned long long acc[4][8];
#pragma unroll
    for (int ip = 0; ip < 4; ip++)
#pragma unroll
        for (int j = 0; j < 8; j++) acc[ip][j] = 0ULL;

    float4 pa0 = *(const float4*)(aRow + lk);
    float4 pa1 = *(const float4*)(aRow + lk + 4);
    float4 pb0 = *(const float4*)(wRow + lk);
    float4 pb1 = *(const float4*)(wRow + lk + 4);

    for (int k0 = 0; k0 < KDIM; k0 += BK) {
        As[lk+0][lr]=pa0.x; As[lk+1][lr]=pa0.y; As[lk+2][lr]=pa0.z; As[lk+3][lr]=pa0.w;
        As[lk+4][lr]=pa1.x; As[lk+5][lr]=pa1.y; As[lk+6][lr]=pa1.z; As[lk+7][lr]=pa1.w;
        Bs[lk+0][lr]=pb0.x; Bs[lk+1][lr]=pb0.y; Bs[lk+2][lr]=pb0.z; Bs[lk+3][lr]=pb0.w;
        Bs[lk+4][lr]=pb1.x; Bs[lk+5][lr]=pb1.y; Bs[lk+6][lr]=pb1.z; Bs[lk+7][lr]=pb1.w;
        __syncthreads();

        if (k0 + BK < KDIM) {
            pa0 = *(const float4*)(aRow + k0 + BK + lk);
            pa1 = *(const float4*)(aRow + k0 + BK + lk + 4);
            pb0 = *(const float4*)(wRow + k0 + BK + lk);
            pb1 = *(const float4*)(wRow + k0 + BK + lk + 4);
        }

#pragma unroll
        for (int kk = 0; kk < BK; kk++) {
            float2 a0 = *(const float2*)&As[kk][ty*4];
            float2 a1 = *(const float2*)&As[kk][ty*4 + 2];
            float2 a2 = *(const float2*)&As[kk][64 + ty*4];
            float2 a3 = *(const float2*)&As[kk][64 + ty*4 + 2];
            float4 b03 = *(const float4*)&Bs[kk][tx*4];
            float4 b47 = *(const float4*)&Bs[kk][64 + tx*4];

            unsigned long long ap[4];
            ap[0] = pk2(a0.x, a0.y); ap[1] = pk2(a1.x, a1.y);
            ap[2] = pk2(a2.x, a2.y); ap[3] = pk2(a3.x, a3.y);
            unsigned long long bb[8];
            bb[0]=pk2(b03.x,b03.x); bb[1]=pk2(b03.y,b03.y);
            bb[2]=pk2(b03.z,b03.z); bb[3]=pk2(b03.w,b03.w);
            bb[4]=pk2(b47.x,b47.x); bb[5]=pk2(b47.y,b47.y);
            bb[6]=pk2(b47.z,b47.z); bb[7]=pk2(b47.w,b47.w);

#pragma unroll
            for (int ip = 0; ip < 4; ip++)
#pragma unroll
                for (int j = 0; j < 8; j++)
                    ffma2(acc[ip][j], ap[ip], bb[j]);
        }
        __syncthreads();
    }

    double sg[5] = {0,0,0,0,0};
    double sd = 0.0;

#pragma unroll
    for (int ip = 0; ip < 4; ip++) {
        const int rbase = ((ip & 2) ? 64 : 0) + ty*4 + ((ip & 1) ? 2 : 0);
#pragma unroll
        for (int half = 0; half < 2; half++) {
            const int r = m0 + rbase + half;
            if (outSlot >= 0) {
                const float* aR = resolveRow(A, aMode, aSlot, r);
                int b = r >> 10, rr = r & 1023;
                size_t gbase = (size_t)(b*NSLOT)*NPB + (size_t)rr*KDIM;
                size_t obase = gbase + (size_t)outSlot*NPB;
#pragma unroll
                for (int jg = 0; jg < 2; jg++) {
                    const int c = n0 + jg*64 + tx*4;
                    float4 av = *(const float4*)(aR + c);
                    float4 bv = *(const float4*)(bias + c);
                    float4 val = unpack4(&acc[ip][jg*4], half, bv);
                    float4 g4;
                    g4.x = val.x - av.x; g4.y = val.y - av.y;
                    g4.z = val.z - av.z; g4.w = val.w - av.w;
                    *(float4*)(g_Fm + obase + c) = val;
                    *(float4*)(g_G  + obase + c) = g4;
#pragma unroll
                    for (int j = 0; j < 5; j++) {
                        float4 gj;
                        if (j == outSlot) gj = g4;
                        else gj = *(const float4*)(g_G + gbase + (size_t)j*NPB + c);
                        sg[j] += (double)(g4.x*gj.x + g4.y*gj.y
                                        + g4.z*gj.z + g4.w*gj.w);
                    }
                    sd += (double)(val.x*val.x + val.y*val.y
                                 + val.z*val.z + val.w*val.w);
                }
            } else {
#pragma unroll
                for (int jg = 0; jg < 2; jg++) {
                    const int c = n0 + jg*64 + tx*4;
                    float4 bv = *(const float4*)(bias + c);
                    float4 val = unpack4(&acc[ip][jg*4], half, bv);
                    *(float4*)(outPlain + (size_t)r*KDIM + c) = val;
                }
            }
        }
    }

    if (outSlot >= 0) {
        const unsigned FULL = 0xFFFFFFFFu;
#pragma unroll
        for (int p = 0; p < 5; p++)
#pragma unroll
            for (int o = 16; o > 0; o >>= 1)
                sg[p] += __shfl_down_sync(FULL, sg[p], o);
#pragma unroll
        for (int o = 16; o > 0; o >>= 1)
            sd += __shfl_down_sync(FULL, sd, o);

        const int wid = tid >> 5, lane = tid & 31;
        if (lane == 0) {
#pragma unroll
            for (int p = 0; p < 5; p++) sred[wid][p] = sg[p];
            sred[wid][5] = sd;
        }
        __syncthreads();
        if (tid < 6) {
            double v = 0.0;
#pragma unroll
            for (int w = 0; w < 8; w++) v += sred[w][tid];
            const int b = m0 >> 10;
            const int chunk = ((blockIdx.y & 7) << 2) | blockIdx.x;
            if (tid < 5) {
                g_gram_part[((size_t)(b*CPB + chunk))*5 + tid] = v;
                if (tid == outSlot) {
                    int bid = blockIdx.y * gridDim.x + blockIdx.x;
                    g_res_part[2*bid] = v;          // sn = pair(slot,slot)
                }
            } else {
                int bid = blockIdx.y * gridDim.x + blockIdx.x;
                g_res_part[2*bid + 1] = v;          // sd
            }
        }
    }
}

// ---------------------------------------------------------------------------
// foldK: init-time fold of fresh pairs (idxPrev, j) into the Gram table.
// ---------------------------------------------------------------------------
__global__ void foldK(int idxPrev)
{
    int tid = threadIdx.x;
    if (tid < 80) {
        int b = tid / 5, j = tid % 5;
        double v = 0.0;
        for (int c = 0; c < CPB; c++)
            v += g_gram_part[((size_t)(b*CPB + c))*5 + j];
        int i_ = idxPrev < j ? idxPrev : j;
        int j_ = idxPrev < j ? j : idxPrev;
        int p = i_*5 - i_*(i_-1)/2 + (j_ - i_);
        g_gramTab[b*15 + p] = v;
    }
}

// ---------------------------------------------------------------------------
// comboSolveK: per-block redundant (residual check + own-batch fold +
// Cholesky) followed by the combination for this block's chunk.
// Grid 512 blocks x 256 thr; block bid serves batch b = bid>>5, seg = bid&31.
// All 32 blocks of a batch compute identical fold/alpha (same inputs, same
// op order); duplicate global writes carry identical bits.
// ---------------------------------------------------------------------------
__global__ __launch_bounds__(256) void comboSolveK(int nk, int idxPrev,
                                                   int doRes, int kIter)
{
    if (g_converged) return;
    __shared__ double sh[256];
    __shared__ double sFresh[5];
    __shared__ float  sAlpha[5];

    const int tid = threadIdx.x;
    const int bid = blockIdx.x;
    const int b   = bid >> 5;
    const int seg = bid & 31;

    // --- residual check (identical in every block) ---
    if (doRes) {
        double sn = 0.0, sd = 0.0;
#pragma unroll
        for (int t = 0; t < 2; t++) {
            int i = t*256 + tid;
            sn += g_res_part[2*i];
            sd += g_res_part[2*i+1];
        }
        sh[tid] = sn; __syncthreads();
        for (int s = 128; s > 0; s >>= 1) { if (tid < s) sh[tid] += sh[tid+s]; __syncthreads(); }
        double tsn = sh[0]; __syncthreads();
        sh[tid] = sd; __syncthreads();
        for (int s = 128; s > 0; s >>= 1) { if (tid < s) sh[tid] += sh[tid+s]; __syncthreads(); }
        double res = sqrt(fmax(sh[0]*0.0 + tsn, 0.0));   // keep exact op order below
        res = sqrt(fmax(tsn, 0.0)) / (1e-5 + sqrt(fmax(sh[0], 0.0)));
        if (bid == 0 && tid == 0) g_diag[700 + (size_t)(kIter-2)] = res;
        if (res < TOLV) {
            if (tid == 0) {
                g_converged = 1;                  // identical write from all blocks
                if (bid == 0) g_diag[20] = (double)kIter;
            }
            return;
        }
        __syncthreads();
    }

    // --- own-batch fold: 5 fresh pairs (idxPrev, j) ---
    if (tid < 5) {
        int j = tid;
        double v = 0.0;
        for (int c = 0; c < CPB; c++)
            v += g_gram_part[((size_t)(b*CPB + c))*5 + j];
        sFresh[j] = v;
        int i_ = idxPrev < j ? idxPrev : j;
        int j_ = idxPrev < j ? j : idxPrev;
        int p = i_*5 - i_*(i_-1)/2 + (j_ - i_);
        g_gramTab[b*15 + p] = v;                  // persist (identical bits)
    }
    __syncthreads();

    // --- own-batch Cholesky -> alpha (thread 0) ---
    if (tid == 0) {
        double Afull[5][5];
        {
            int p = 0;
            for (int i = 0; i < 5; i++)
                for (int j = i; j < 5; j++) {
                    // fresh entries use locally computed values; stale from table
                    int fi = idxPrev < j ? idxPrev : j;   // not used; compute p-match
                    (void)fi;
                    double v;
                    int ii = i, jj = j;
                    bool fresh = (ii == idxPrev) || (jj == idxPrev);
                    if (fresh) {
                        int other = (ii == idxPrev) ? jj : ii;
                        v = sFresh[other];
                    } else {
                        v = g_gramTab[b*15 + p];
                    }
                    p++;
                    Afull[i][j] = v; Afull[j][i] = v;
                }
            for (int i = 0; i < 5; i++) Afull[i][i] += LAMBDA;
        }
        double L[5][5];
        for (int c = 0; c < nk; c++) {
            double d = Afull[c][c];
            for (int q = 0; q < c; q++) d -= L[c][q]*L[c][q];
            d = sqrt(fmax(d, 1e-300));
            L[c][c] = d;
            for (int r = c+1; r < nk; r++) {
                double v = Afull[r][c];
                for (int q = 0; q < c; q++) v -= L[r][q]*L[c][q];
                L[r][c] = v / d;
            }
        }
        double y[5];
        for (int r = 0; r < nk; r++) {
            double v = 1.0;
            for (int j = 0; j < r; j++) v -= L[r][j]*y[j];
            y[r] = v / L[r][r];
        }
        double z[5];
        for (int r = nk-1; r >= 0; r--) {
            double v = y[r];
            for (int j = r+1; j < nk; j++) v -= L[j][r]*z[j];
            z[r] = v / L[r][r];
        }
        double S = 0.0;
        for (int r = 0; r < nk; r++) S += z[r];
        for (int m = 0; m < 5; m++)
            sAlpha[m] = (m < nk) ? (float)(z[m]/S) : 0.f;
    }
    __syncthreads();

    // --- combination for this block's segment ---
    float al[5];
#pragma unroll
    for (int m = 0; m < 5; m++) al[m] = sAlpha[m];

    const float4* Fb = ((const float4*)g_Fm) + (size_t)b*NSLOT*NPB4;
#pragma unroll 4
    for (int t = 0; t < 16; t++) {
        int off = seg*4096 + t*256 + tid;
        float4 acc = make_float4(0.f,0.f,0.f,0.f);
#pragma unroll
        for (int m = 0; m < 5; m++) {
            if (m < nk) {
                float4 v = Fb[(size_t)m*NPB4 + off];
                acc.x = fmaf(al[m], v.x, acc.x);
                acc.y = fmaf(al[m], v.y, acc.y);
                acc.z = fmaf(al[m], v.z, acc.z);
                acc.w = fmaf(al[m], v.w, acc.w);
            }
        }
        ((float4*)g_xlast)[(size_t)b*NPB4 + off] = acc;
    }
}

// ---------------------------------------------------------------------------
extern "C" void kernel_launch(void* const* d_in, const int* in_sizes, int n_in,
                              void* d_out, int out_size)
{
    const float* x      = (const float*)d_in[0];
    const float* lin_w  = (const float*)d_in[1];
    const float* lin_b  = (const float*)d_in[2];
    const float* weight = (const float*)d_in[3];
    const float* bias   = (const float*)d_in[4];
    float* out = (float*)d_out;

    cudaStreamCaptureStatus cap = cudaStreamCaptureStatusNone;
    cudaStreamIsCapturing(0, &cap);
    const bool capturing = (cap != cudaStreamCaptureStatusNone);

    dim3 gg(KDIM/BN, MROW/BM);   // (4, 128)

    resetK<<<1, 1>>>();

    // init: Fm0 = f(x) (pairs (0,.)), fold; Fm1 = f(Fm0) (pairs (1,.))
    gemm128<<<gg, 256>>>(x,       0, 0, lin_w, lin_b, nullptr, 0, 0);
    foldK  <<<1, 96>>>(0);
    gemm128<<<gg, 256>>>(nullptr, 1, 0, lin_w, lin_b, nullptr, 1, 0);

    for (int k = 2; k < 50; k++) {
        int nk  = (k < 5) ? k : 5;
        int idx = k % 5;
        int idxPrev = (k == 2) ? 1 : ((k - 1) % 5);
        comboSolveK<<<512, 256>>>(nk, idxPrev, (k > 2) ? 1 : 0, k);
        gemm128    <<<gg, 256>>>(nullptr, 2, 0, lin_w, lin_b, nullptr, idx, 1);
    }

    gemm128<<<gg, 256>>>(nullptr, 2, 0, weight, bias, out, -1, 0);

    // Fail-only diagnostics (zero cost when converged).
    if (!capturing) {
        cudaDeviceSynchronize();
        static double h[1024];
        cudaMemcpyFromSymbol(h, g_diag, sizeof(h));
        if (h[20] < 0.0) {
            for (int k = 49; k >= 3; k--)
                fprintf(stderr, "D k=%d res=%.3e\n", k, h[700 + (size_t)(k-2)]);
            fprintf(stderr, "D SUMMARY convk=%.0f\n", h[20]);
            fflush(stderr);
            exit(42);
        }
    }
}